// round 1
// baseline (speedup 1.0000x reference)
#include <cuda_runtime.h>
#include <cuda_bf16.h>

// DistMult scoring: out[b] = sum_d src[b,d] * M[rel_idx, d] * dst[b,d]
// B = 500000, D = 128. Pure HBM-bound stream (~514 MB traffic).
//
// One warp per row:
//   lane l loads float4 of src and dst at element 4*l (coalesced 512B/warp/tensor),
//   rel float4 comes from L2/L1 (same 512B for every warp),
//   butterfly shuffle-reduce, lane 0 stores.

__global__ __launch_bounds__(256) void distmult_kernel(
    const float4* __restrict__ src4,
    const float4* __restrict__ dst4,
    const float4* __restrict__ M4,
    const int* __restrict__ rel_idx,
    float* __restrict__ out,
    int B)
{
    const int gtid = blockIdx.x * blockDim.x + threadIdx.x;
    const int row  = gtid >> 5;      // warp id = row
    const int lane = threadIdx.x & 31;
    if (row >= B) return;

    const int r = __ldg(rel_idx);    // broadcast scalar, L2-resident

    // D=128 floats = 32 float4 per row; lane l takes float4 #l.
    const long base = (long)row * 32 + lane;
    const float4 s = __ldg(&src4[base]);
    const float4 d = __ldg(&dst4[base]);
    const float4 m = __ldg(&M4[(long)r * 32 + lane]);

    float p = s.x * m.x * d.x;
    p = fmaf(s.y * m.y, d.y, p);
    p = fmaf(s.z * m.z, d.z, p);
    p = fmaf(s.w * m.w, d.w, p);

    // warp butterfly reduction
    #pragma unroll
    for (int off = 16; off > 0; off >>= 1)
        p += __shfl_xor_sync(0xffffffffu, p, off);

    if (lane == 0) out[row] = p;
}

extern "C" void kernel_launch(void* const* d_in, const int* in_sizes, int n_in,
                              void* d_out, int out_size)
{
    // metadata order: src_emb [B,128] f32, dst_emb [B,128] f32, M [1000,128] f32, rel_idx int32
    const float4* src4 = (const float4*)d_in[0];
    const float4* dst4 = (const float4*)d_in[1];
    const float4* M4   = (const float4*)d_in[2];
    const int* rel_idx = (const int*)d_in[3];
    float* out = (float*)d_out;

    const int B = in_sizes[0] / 128;          // 500000
    const int warps_per_block = 256 / 32;     // 8 rows per block
    const int blocks = (B + warps_per_block - 1) / warps_per_block;

    distmult_kernel<<<blocks, 256>>>(src4, dst4, M4, rel_idx, out, B);
}